// round 16
// baseline (speedup 1.0000x reference)
#include <cuda_runtime.h>
#include <cstdint>

#define N_ANCH   100800
#define D_COLS   117
#define NC       80
#define NM       32
#define TOPK     4096
#define MAX_DET  300
#define CONF_T   0.25f
#define IOU_T    0.45f
#define CAND_CAP 8192
#define NWORDS   128            // TOPK/32
#define MBLK     148
#define MTHR     1024
#define MTOT     (MBLK * MTHR)  // 151552
#define MWARPS   (MBLK * 32)    // 4736
#define SROWS    64             // rows per score block
#define SBLK     (N_ANCH / SROWS)         // 1575
#define SF4      ((SROWS * D_COLS) / 4)   // 1872 float4 per tile

// ---------------- scratch (static __device__ — no allocation) ----------------
__device__ float              g_score[N_ANCH];
__device__ float              g_cls[N_ANCH];
__device__ unsigned int       g_hist[65536];          // zero at init; re-zeroed each run
__device__ unsigned int       g_chunk[64];            // reset by last score block
__device__ unsigned int       g_done;                 // score completion ticket
__device__ unsigned int       g_tb;                   // threshold bucket
__device__ unsigned int       g_ncand;                // reset each run (phase D)
__device__ unsigned long long g_cand[CAND_CAP];
__device__ int                g_top_idx[TOPK];
__device__ float              g_top_s[TOPK];
__device__ float              g_by1[TOPK], g_bx1[TOPK], g_by2[TOPK], g_bx2[TOPK], g_bar_a[TOPK];
__device__ unsigned int       g_maskT[NWORDS * TOPK]; // [jword][row]; lower triangle unused
__device__ int                g_out_pos[MAX_DET];
__device__ unsigned char      g_out_keep[MAX_DET];

__device__ unsigned int          g_bar_count;
__device__ volatile unsigned int g_bar_gen;

// ---------------- helpers ----------------
__device__ __forceinline__ unsigned int f2key(float f) {
    unsigned int b = __float_as_uint(f);
    return b ^ ((b >> 31) ? 0xFFFFFFFFu : 0x80000000u);
}
__device__ __forceinline__ float key2f(unsigned int k) {
    unsigned int b = (k & 0x80000000u) ? (k ^ 0x80000000u) : ~k;
    return __uint_as_float(b);
}
__device__ __forceinline__ void grid_bar() {
    __syncthreads();
    if (threadIdx.x == 0) {
        unsigned int gen = g_bar_gen;
        __threadfence();
        unsigned int t = atomicAdd(&g_bar_count, 1u);
        if (t == MBLK - 1) {
            g_bar_count = 0;
            __threadfence();
            g_bar_gen = gen + 1;
        } else {
            while (g_bar_gen == gen) { }
        }
        __threadfence();
    }
    __syncthreads();
}

// ---------------- node 1: score/class + hist + (last block) threshold -------
__global__ void __launch_bounds__(256) k_score(const float* __restrict__ x) {
    __shared__ float        tile[SROWS * D_COLS];   // 29952 B
    __shared__ unsigned int s_chunk[64];
    __shared__ unsigned int s_sufg[256];
    __shared__ int          s_c, s_g, s_last;
    __shared__ unsigned int s_rem;
    const int bid = blockIdx.x;
    const int tid = threadIdx.x;

    if (tid < 64) s_chunk[tid] = 0u;

    const float4* src = (const float4*)(x + (size_t)bid * SROWS * D_COLS);
    float4 v[8];
#pragma unroll
    for (int k = 0; k < 8; k++) {
        int i = tid + k * 256;
        if (i < SF4) v[k] = src[i];
    }
    float4* dst4 = (float4*)tile;
#pragma unroll
    for (int k = 0; k < 8; k++) {
        int i = tid + k * 256;
        if (i < SF4) dst4[i] = v[k];
    }
    __syncthreads();

    const int r = tid >> 2, q = tid & 3;
    const float* row = tile + r * D_COLS;
    float obj = row[4];

    float best = -1.0f; int bc = NC;
#pragma unroll
    for (int k = 0; k < 20; k++) {
        int c = q * 20 + k;
        float p = __fmul_rn(row[5 + c], obj);
        if (p > best) { best = p; bc = c; }     // strict > : first index wins
    }
#pragma unroll
    for (int off = 1; off <= 2; off <<= 1) {
        float ov = __shfl_xor_sync(0xFFFFFFFFu, best, off);
        int   oc = __shfl_xor_sync(0xFFFFFFFFu, bc,   off);
        if (ov > best || (ov == best && oc < bc)) { best = ov; bc = oc; }
    }
    if (q == 0) {
        int ga = bid * SROWS + r;
        float sc = (obj > CONF_T) ? best : -1.0f;
        g_score[ga] = sc;
        g_cls[ga]   = (float)bc;
        unsigned int key16 = f2key(sc) >> 16;
        atomicAdd(&g_hist[key16], 1u);
        atomicAdd(&s_chunk[key16 >> 10], 1u);
    }
    __syncthreads();
    if (tid < 64 && s_chunk[tid]) atomicAdd(&g_chunk[tid], s_chunk[tid]);

    __syncthreads();
    if (tid == 0) {
        __threadfence();
        s_last = (atomicAdd(&g_done, 1u) == SBLK - 1);
    }
    __syncthreads();
    if (!s_last) return;

    if (tid == 0) {
        unsigned int cum = 0; int c = 0; unsigned int rem = TOPK;
        for (int b = 63; b >= 0; b--) {
            unsigned int cb = g_chunk[b];
            if (cum + cb >= TOPK) { c = b; rem = TOPK - cum; break; }
            cum += cb;
        }
        s_c = c; s_rem = rem;
    }
    __syncthreads();
    {
        int c = s_c;
        unsigned int grp = 0;
#pragma unroll
        for (int k = 0; k < 4; k++) grp += g_hist[c * 1024 + tid * 4 + k];
        s_sufg[tid] = grp;
        __syncthreads();
        for (int off = 1; off < 256; off <<= 1) {
            unsigned int vv = (tid + off < 256) ? s_sufg[tid + off] : 0u;
            __syncthreads();
            s_sufg[tid] += vv;
            __syncthreads();
        }
        unsigned int rem = s_rem;
        if (s_sufg[tid] >= rem && (tid == 255 || s_sufg[tid + 1] < rem)) s_g = tid;
        __syncthreads();
        if (tid == 0) {
            int g = s_g;
            unsigned int cum = (g == 255) ? 0u : s_sufg[g + 1];
            int T = c * 1024 + g * 4;
            for (int b = g * 4 + 3; b >= g * 4; b--) {
                cum += g_hist[c * 1024 + b];
                if (cum >= rem) { T = c * 1024 + b; break; }
            }
            g_tb = (unsigned int)T;
            g_done = 0u;
        }
        if (tid < 64) g_chunk[tid] = 0u;
    }
}

// ---------------- node 2: everything else, one persistent kernel -------------
__global__ void __launch_bounds__(MTHR, 1) k_mega(const float* __restrict__ x,
                                                  float* __restrict__ out) {
    __shared__ unsigned long long s_tile[MTHR];                        // 8 KB (BC)
    __shared__ float e_y1[32][32], e_x1[32][32], e_y2[32][32], e_x2[32][32], e_ar[32][32]; // 20KB (D)
    __shared__ unsigned int       s_rm[NWORDS];
    __shared__ unsigned int       s_kept[NWORDS];
    __shared__ int                s_tot[NWORDS];

    const int tid  = threadIdx.x;
    const int bid  = blockIdx.x;
    const int gid  = bid * MTHR + tid;
    const int lane = tid & 31;
    const int wid  = tid >> 5;

    // ---- A: compact candidates (warp-aggregated append) ----
    {
        unsigned int tb = g_tb;
        unsigned int k = (gid < N_ANCH) ? f2key(g_score[gid]) : 0u;
        bool pred = (gid < N_ANCH) && ((k >> 16) >= tb);
        unsigned int mask = __ballot_sync(0xFFFFFFFFu, pred);
        if (pred) {
            int leader = __ffs(mask) - 1;
            unsigned int base = 0;
            if (lane == leader) base = atomicAdd(&g_ncand, (unsigned)__popc(mask));
            base = __shfl_sync(mask, base, leader);
            unsigned int pos = base + __popc(mask & ((1u << lane) - 1u));
            if (pos < CAND_CAP)
                g_cand[pos] = ((unsigned long long)k << 32) | (unsigned int)(~gid);
        }
    }
    grid_bar();

    // ---- BC: full rank per block + immediate scatter/box gather ----
    {
        unsigned int n = g_ncand; if (n > CAND_CAP) n = CAND_CAP;
        unsigned int cpb = (n + MBLK - 1) / MBLK;              // <= 56
        unsigned int lo = bid * cpb;
        unsigned int hi = lo + cpb; if (hi > n) hi = n;
        unsigned int c0 = lo + wid, c1 = lo + wid + 32;
        unsigned long long my0 = (c0 < hi) ? g_cand[c0] : 0ULL;
        unsigned long long my1 = (c1 < hi) ? g_cand[c1] : 0ULL;
        unsigned int cnt0 = 0, cnt1 = 0;
        for (unsigned int base = 0; base < n; base += MTHR) {
            unsigned int idx = base + tid;
            s_tile[tid] = (idx < n) ? g_cand[idx] : 0ULL;
            __syncthreads();
            unsigned int lim = (n - base < (unsigned)MTHR) ? (n - base) : (unsigned)MTHR;
            for (unsigned int k = lane; k < lim; k += 32) {
                unsigned long long v = s_tile[k];
                cnt0 += (v > my0);
                cnt1 += (v > my1);
            }
            __syncthreads();
        }
#pragma unroll
        for (int off = 16; off; off >>= 1) {
            cnt0 += __shfl_xor_sync(0xFFFFFFFFu, cnt0, off);
            cnt1 += __shfl_xor_sync(0xFFFFFFFFu, cnt1, off);
        }
        // lane 0 scatters c0, lane 1 scatters c1 (counts valid on all lanes)
        unsigned long long myc = (lane == 0) ? my0 : my1;
        unsigned int rank = (lane == 0) ? cnt0 : cnt1;
        unsigned int cc   = (lane == 0) ? c0 : c1;
        if (lane < 2 && cc < hi && rank < TOPK) {
            int a = (int)(~(unsigned int)myc);
            g_top_s[rank]   = key2f((unsigned int)(myc >> 32));
            g_top_idx[rank] = a;
            const float* row = x + (size_t)a * D_COLS;
            float xc = row[0], yc = row[1], w = row[2], h = row[3];
            float hh = __fmul_rn(h, 0.5f), hw = __fmul_rn(w, 0.5f);
            float y1 = __fsub_rn(yc, hh), x1 = __fsub_rn(xc, hw);
            float y2 = __fadd_rn(yc, hh), x2 = __fadd_rn(xc, hw);
            g_by1[rank] = y1; g_bx1[rank] = x1; g_by2[rank] = y2; g_bx2[rank] = x2;
            g_bar_a[rank] = __fmul_rn(__fsub_rn(y2, y1), __fsub_rn(x2, x1));
        }
    }
    grid_bar();

    // ---- D: suppression bitmask (upper triangle) + counter resets ----
    {
        if (gid < 65536) g_hist[gid] = 0u;       // safe: k_score finished before launch
        if (gid == 0)    g_ncand = 0u;           // safe: all blocks read it before bar2
        int gwm = bid * 32 + wid;
        for (int g = gwm; g < 16384; g += MWARPS) {
            int rg = g >> 7;
            int w  = g & 127;
            if (w < rg) continue;                 // lower triangle never read by E
            int i  = (rg << 5) | lane;

            int jj = (w << 5) + lane;
            e_y1[wid][lane] = g_by1[jj]; e_x1[wid][lane] = g_bx1[jj];
            e_y2[wid][lane] = g_by2[jj]; e_x2[wid][lane] = g_bx2[jj];
            e_ar[wid][lane] = g_bar_a[jj];
            __syncwarp();

            float ry1 = g_by1[i], rx1 = g_bx1[i], ry2 = g_by2[i], rx2 = g_bx2[i];
            float rar = g_bar_a[i];
            bool  diag = (w == rg);

            unsigned int word = 0;
#pragma unroll 4
            for (int k = 0; k < 32; k++) {
                if (diag && k <= lane) continue;
                float yy1 = fmaxf(ry1, e_y1[wid][k]);
                float xx1 = fmaxf(rx1, e_x1[wid][k]);
                float yy2 = fminf(ry2, e_y2[wid][k]);
                float xx2 = fminf(rx2, e_x2[wid][k]);
                float dh  = fmaxf(__fsub_rn(yy2, yy1), 0.0f);
                float dw  = fmaxf(__fsub_rn(xx2, xx1), 0.0f);
                float it  = __fmul_rn(dh, dw);
                if (it > 0.0f) {
                    float un  = __fsub_rn(__fadd_rn(rar, e_ar[wid][k]), it);
                    float unc = fmaxf(un, 1e-9f);
                    float c   = __fmul_rn(IOU_T, unc);
                    bool  sup;
                    if (fabsf(__fsub_rn(it, c)) > 1e-4f * c) {
                        sup = (it > c);                       // far from boundary
                    } else {
                        sup = (__fdiv_rn(it, unc) > IOU_T);   // exact ref rounding
                    }
                    if (sup) word |= 1u << k;
                }
            }
            g_maskT[w * TOPK + i] = word;
            __syncwarp();
        }
    }
    grid_bar();
    if (bid != 0) return;          // blocks 1..147 done; block 0 finishes alone

    // ---- E: greedy sweep, early-stop at 300 kept (block 0) ----
    {
        bool act = tid < 128;
        unsigned int init_rm = 0, acc = 0;
        const uint4* rbase = (const uint4*)g_maskT + (size_t)(act ? tid : 0) * (TOPK / 4);
        if (act) {
#pragma unroll 4
            for (int b = 0; b < 32; b++)
                if (!(g_top_s[tid * 32 + b] > -0.5f)) init_rm |= 1u << b;
        }
        int wstop = NWORDS;
#pragma unroll 1
        for (int w = 0; w < NWORDS; w++) {
            unsigned int A[32];
            bool mine = act && tid >= w;           // words t<w are structurally zero
            if (mine) {
#pragma unroll
                for (int q = 0; q < 8; q++) {
                    uint4 v = rbase[w * 8 + q];
                    A[q*4+0] = v.x; A[q*4+1] = v.y; A[q*4+2] = v.z; A[q*4+3] = v.w;
                }
            }
            if (tid == w) {
                unsigned int rm = init_rm | acc;
                unsigned int kept = 0;
#pragma unroll
                for (int b = 0; b < 32; b++) {
                    if (!((rm >> b) & 1u)) { kept |= 1u << b; rm |= A[b]; }
                }
                s_rm[w] = rm; s_kept[w] = kept;
                s_tot[w] = (w ? s_tot[w - 1] : 0) + __popc(kept);
            }
            __syncthreads();
            if (s_tot[w] >= MAX_DET) { wstop = w + 1; break; }
            if (mine) {
                unsigned int kk = s_kept[w];
#pragma unroll
                for (int b = 0; b < 32; b++)
                    acc |= ((kk >> b) & 1u) ? A[b] : 0u;
            }
        }
        __syncthreads();
        if (tid == 0) {            // top-300: kept first (score-desc), then pad
            int cnt = 0;
            for (int w = 0; w < wstop && cnt < MAX_DET; w++) {
                unsigned int kept = s_kept[w];
                while (kept && cnt < MAX_DET) {
                    int b = __ffs(kept) - 1; kept &= kept - 1;
                    g_out_pos[cnt] = (w << 5) | b; g_out_keep[cnt] = 1; cnt++;
                }
            }
            for (int w = 0; w < wstop && cnt < MAX_DET; w++) {      // pad (full sweep only)
                unsigned int dead = s_rm[w];
                while (dead && cnt < MAX_DET) {
                    int b = __ffs(dead) - 1; dead &= dead - 1;
                    g_out_pos[cnt] = (w << 5) | b; g_out_keep[cnt] = 0; cnt++;
                }
            }
        }
    }
    __syncthreads();

    // ---- F: final gather -> out (block 0's 32 warps, ~10 rounds) ----
    for (int gw = wid; gw < MAX_DET; gw += 32) {
        int pos = g_out_pos[gw];
        int a   = g_top_idx[pos];
        const float* row = x + (size_t)a * D_COLS;
        if (lane == 0) {
            float xc = row[0], yc = row[1], w = row[2], h = row[3];
            float hh = __fmul_rn(h, 0.5f), hw = __fmul_rn(w, 0.5f);
            out[gw * 4 + 0] = __fsub_rn(yc, hh);
            out[gw * 4 + 1] = __fsub_rn(xc, hw);
            out[gw * 4 + 2] = __fadd_rn(yc, hh);
            out[gw * 4 + 3] = __fadd_rn(xc, hw);
            out[MAX_DET * 4 + gw] = g_cls[a];
            out[MAX_DET * 5 + gw] = g_out_keep[gw] ? g_top_s[pos] : -1.0f;
        }
        out[MAX_DET * 6 + gw * NM + lane] = row[5 + NC + lane];
    }
}

// ---------------- launch ----------------
extern "C" void kernel_launch(void* const* d_in, const int* in_sizes, int n_in,
                              void* d_out, int out_size) {
    const float* x = (const float*)d_in[0];
    float* out = (float*)d_out;

    k_score <<<SBLK, 256>>>(x);
    k_mega  <<<MBLK, MTHR>>>(x, out);
}